// round 2
// baseline (speedup 1.0000x reference)
#include <cuda_runtime.h>
#include <cstdint>

// Problem constants
#define SDIM 2048
#define DDIM 64
#define BHDIM 32         // B*H = 2*16
#define BM 128           // query rows per CTA
#define BN 64            // keys per iteration
#define NITER (SDIM/BN)  // 32
#define THREADS 256      // 8 warps, 16 query rows each
#define QSTRIDE 68       // floats per row (conflict-free A/B frag loads)
#define KSTRIDE 68
#define VSTRIDE 72

#define SMEM_FLOATS (BM*QSTRIDE + 2*BN*KSTRIDE + 2*BN*VSTRIDE)
#define SMEM_BYTES  (SMEM_FLOATS*4)

__device__ __forceinline__ uint32_t f2tf32(float f) {
    uint32_t r;
    asm("cvt.rna.tf32.f32 %0, %1;" : "=r"(r) : "f"(f));
    return r;
}

__device__ __forceinline__ void mma_tf32(float d[4],
                                         uint32_t a0, uint32_t a1, uint32_t a2, uint32_t a3,
                                         uint32_t b0, uint32_t b1) {
    asm volatile(
        "mma.sync.aligned.m16n8k8.row.col.f32.tf32.tf32.f32 "
        "{%0,%1,%2,%3},{%4,%5,%6,%7},{%8,%9},{%0,%1,%2,%3};\n"
        : "+f"(d[0]), "+f"(d[1]), "+f"(d[2]), "+f"(d[3])
        : "r"(a0), "r"(a1), "r"(a2), "r"(a3), "r"(b0), "r"(b1));
}

__device__ __forceinline__ void cp16(uint32_t saddr, const void* g) {
    asm volatile("cp.async.cg.shared.global [%0], [%1], 16;\n" :: "r"(saddr), "l"(g));
}

__global__ void __launch_bounds__(THREADS, 2)
attn_kernel(const float* __restrict__ Q, const float* __restrict__ K,
            const float* __restrict__ V, const int* __restrict__ M,
            float* __restrict__ O)
{
    extern __shared__ float smem[];
    float* QS = smem;                         // BM x QSTRIDE (tf32-converted)
    float* KS = smem + BM * QSTRIDE;          // 2 x BN x KSTRIDE (raw fp32)
    float* VS = KS + 2 * BN * KSTRIDE;        // 2 x BN x VSTRIDE (raw fp32)

    const int tid  = threadIdx.x;
    const int warp = tid >> 5;
    const int lane = tid & 31;
    const int gi   = lane >> 2;   // groupID (0..7)
    const int ci   = lane & 3;    // threadID_in_group (0..3)

    const int q0 = blockIdx.x * BM;
    const int bh = blockIdx.y;

    const size_t baseQ  = ((size_t)bh * SDIM + q0) * DDIM;
    const size_t baseKV = (size_t)bh * SDIM * DDIM;
    const size_t baseM  = (size_t)bh * SDIM * SDIM;

    const uint32_t ksBase = (uint32_t)__cvta_generic_to_shared(KS);
    const uint32_t vsBase = (uint32_t)__cvta_generic_to_shared(VS);

    // ---- prologue: async-load K/V tile 0 into stage 0 ----
    {
#pragma unroll
        for (int i = 0; i < 4; i++) {
            int idx = i * THREADS + tid;          // 0..1023
            int row = idx >> 4;
            int c4  = (idx & 15) << 2;
            cp16(ksBase + (uint32_t)(row * KSTRIDE + c4) * 4u, K + baseKV + (size_t)row * DDIM + c4);
            cp16(vsBase + (uint32_t)(row * VSTRIDE + c4) * 4u, V + baseKV + (size_t)row * DDIM + c4);
        }
        asm volatile("cp.async.commit_group;\n");
    }

    // ---- load Q tile once, convert to tf32 in smem ----
#pragma unroll
    for (int i = 0; i < 8; i++) {
        int idx = i * THREADS + tid;              // 0..2047
        int row = idx >> 4;
        int c4  = (idx & 15) << 2;
        float4 v = *reinterpret_cast<const float4*>(Q + baseQ + (size_t)row * DDIM + c4);
        float4 w;
        w.x = __uint_as_float(f2tf32(v.x));
        w.y = __uint_as_float(f2tf32(v.y));
        w.z = __uint_as_float(f2tf32(v.z));
        w.w = __uint_as_float(f2tf32(v.w));
        *reinterpret_cast<float4*>(QS + row * QSTRIDE + c4) = w;
    }

    const float NEG_INF = __int_as_float(0xff800000);
    float oacc[8][4];
#pragma unroll
    for (int i = 0; i < 8; i++)
#pragma unroll
        for (int j = 0; j < 4; j++) oacc[i][j] = 0.f;
    float m0 = NEG_INF, m1 = NEG_INF, l0 = 0.f, l1 = 0.f;

    const float* qrow0 = QS + (warp * 16 + gi) * QSTRIDE;
    const float* qrow1 = qrow0 + 8 * QSTRIDE;
    // mask is int32 (harness widens jax bool -> int32); per-thread base at col 2*ci
    const int* mrow0 = M + baseM + (size_t)(q0 + warp * 16 + gi) * SDIM + 2 * ci;
    const int* mrow1 = mrow0 + (size_t)8 * SDIM;

    const int srcA = 4 * gi + (ci >> 1);
    const int srcB = srcA + 2;
    const bool odd = (ci & 1);

    for (int it = 0; it < NITER; ++it) {
        const int st = it & 1;
        asm volatile("cp.async.wait_group 0;\n");
        __syncthreads();

        // prefetch next tile into the other stage (overlaps with compute below)
        if (it + 1 < NITER) {
            const int k0n = (it + 1) * BN;
            const uint32_t kd = ksBase + (uint32_t)((st ^ 1) * BN * KSTRIDE) * 4u;
            const uint32_t vd = vsBase + (uint32_t)((st ^ 1) * BN * VSTRIDE) * 4u;
#pragma unroll
            for (int i = 0; i < 4; i++) {
                int idx = i * THREADS + tid;
                int row = idx >> 4;
                int c4  = (idx & 15) << 2;
                cp16(kd + (uint32_t)(row * KSTRIDE + c4) * 4u,
                     K + baseKV + (size_t)(k0n + row) * DDIM + c4);
                cp16(vd + (uint32_t)(row * VSTRIDE + c4) * 4u,
                     V + baseKV + (size_t)(k0n + row) * DDIM + c4);
            }
            asm volatile("cp.async.commit_group;\n");
        }

        const float* Kst = KS + st * BN * KSTRIDE;
        const float* Vst = VS + st * BN * VSTRIDE;

        // ---- S = Q K^T  (16 x 64 per warp) ----
        float sacc[8][4];
#pragma unroll
        for (int i = 0; i < 8; i++)
#pragma unroll
            for (int j = 0; j < 4; j++) sacc[i][j] = 0.f;

#pragma unroll
        for (int k = 0; k < 8; k++) {
            uint32_t a0 = __float_as_uint(qrow0[8 * k + ci]);
            uint32_t a1 = __float_as_uint(qrow1[8 * k + ci]);
            uint32_t a2 = __float_as_uint(qrow0[8 * k + ci + 4]);
            uint32_t a3 = __float_as_uint(qrow1[8 * k + ci + 4]);
#pragma unroll
            for (int nt = 0; nt < 8; nt++) {
                const float* kr = Kst + (8 * nt + gi) * KSTRIDE + 8 * k + ci;
                uint32_t b0 = f2tf32(kr[0]);
                uint32_t b1 = f2tf32(kr[4]);
                mma_tf32(sacc[nt], a0, a1, a2, a3, b0, b1);
            }
        }

        // ---- mask + scale (mask int32: nonzero -> -1e9, else s * 1/sqrt(64)) ----
        const int kbase = it * BN;
#pragma unroll
        for (int nt = 0; nt < 8; nt++) {
            int2 mm0 = *reinterpret_cast<const int2*>(mrow0 + kbase + 8 * nt);
            int2 mm1 = *reinterpret_cast<const int2*>(mrow1 + kbase + 8 * nt);
            sacc[nt][0] = mm0.x ? -1e9f : sacc[nt][0] * 0.125f;
            sacc[nt][1] = mm0.y ? -1e9f : sacc[nt][1] * 0.125f;
            sacc[nt][2] = mm1.x ? -1e9f : sacc[nt][2] * 0.125f;
            sacc[nt][3] = mm1.y ? -1e9f : sacc[nt][3] * 0.125f;
        }

        // ---- online softmax ----
        float rm0 = NEG_INF, rm1 = NEG_INF;
#pragma unroll
        for (int nt = 0; nt < 8; nt++) {
            rm0 = fmaxf(rm0, fmaxf(sacc[nt][0], sacc[nt][1]));
            rm1 = fmaxf(rm1, fmaxf(sacc[nt][2], sacc[nt][3]));
        }
        rm0 = fmaxf(rm0, __shfl_xor_sync(0xffffffffu, rm0, 1));
        rm0 = fmaxf(rm0, __shfl_xor_sync(0xffffffffu, rm0, 2));
        rm1 = fmaxf(rm1, __shfl_xor_sync(0xffffffffu, rm1, 1));
        rm1 = fmaxf(rm1, __shfl_xor_sync(0xffffffffu, rm1, 2));

        float mn0 = fmaxf(m0, rm0), mn1 = fmaxf(m1, rm1);
        float al0 = __expf(m0 - mn0), al1 = __expf(m1 - mn1);

        float rs0 = 0.f, rs1 = 0.f;
#pragma unroll
        for (int nt = 0; nt < 8; nt++) {
            sacc[nt][0] = __expf(sacc[nt][0] - mn0);
            sacc[nt][1] = __expf(sacc[nt][1] - mn0);
            sacc[nt][2] = __expf(sacc[nt][2] - mn1);
            sacc[nt][3] = __expf(sacc[nt][3] - mn1);
            rs0 += sacc[nt][0] + sacc[nt][1];
            rs1 += sacc[nt][2] + sacc[nt][3];
        }
        rs0 += __shfl_xor_sync(0xffffffffu, rs0, 1);
        rs0 += __shfl_xor_sync(0xffffffffu, rs0, 2);
        rs1 += __shfl_xor_sync(0xffffffffu, rs1, 1);
        rs1 += __shfl_xor_sync(0xffffffffu, rs1, 2);

        l0 = l0 * al0 + rs0;
        l1 = l1 * al1 + rs1;
        m0 = mn0; m1 = mn1;

#pragma unroll
        for (int nd = 0; nd < 8; nd++) {
            oacc[nd][0] *= al0; oacc[nd][1] *= al0;
            oacc[nd][2] *= al1; oacc[nd][3] *= al1;
        }

        // ---- O += P V : move P from C-layout to A-layout via shuffles ----
#pragma unroll
        for (int kk = 0; kk < 8; kk++) {
            float v00 = __shfl_sync(0xffffffffu, sacc[kk][0], srcA);
            float v01 = __shfl_sync(0xffffffffu, sacc[kk][1], srcA);
            float v10 = __shfl_sync(0xffffffffu, sacc[kk][2], srcA);
            float v11 = __shfl_sync(0xffffffffu, sacc[kk][3], srcA);
            float w00 = __shfl_sync(0xffffffffu, sacc[kk][0], srcB);
            float w01 = __shfl_sync(0xffffffffu, sacc[kk][1], srcB);
            float w10 = __shfl_sync(0xffffffffu, sacc[kk][2], srcB);
            float w11 = __shfl_sync(0xffffffffu, sacc[kk][3], srcB);
            uint32_t a0 = f2tf32(odd ? v01 : v00);
            uint32_t a1 = f2tf32(odd ? v11 : v10);
            uint32_t a2 = f2tf32(odd ? w01 : w00);
            uint32_t a3 = f2tf32(odd ? w11 : w10);

            const float* vr0 = Vst + (8 * kk + ci) * VSTRIDE + gi;
            const float* vr1 = vr0 + 4 * VSTRIDE;
#pragma unroll
            for (int nd = 0; nd < 8; nd++) {
                uint32_t b0 = f2tf32(vr0[8 * nd]);
                uint32_t b1 = f2tf32(vr1[8 * nd]);
                mma_tf32(oacc[nd], a0, a1, a2, a3, b0, b1);
            }
        }
    }

    // ---- epilogue: O / l ----
    const float il0 = 1.f / l0;
    const float il1 = 1.f / l1;
    float* o0 = O + ((size_t)bh * SDIM + q0 + warp * 16 + gi) * DDIM;
    float* o1 = o0 + 8 * DDIM;
#pragma unroll
    for (int nd = 0; nd < 8; nd++) {
        int col = 8 * nd + 2 * ci;
        float2 r0 = make_float2(oacc[nd][0] * il0, oacc[nd][1] * il0);
        float2 r1 = make_float2(oacc[nd][2] * il1, oacc[nd][3] * il1);
        *reinterpret_cast<float2*>(o0 + col) = r0;
        *reinterpret_cast<float2*>(o1 + col) = r1;
    }
}

extern "C" void kernel_launch(void* const* d_in, const int* in_sizes, int n_in,
                              void* d_out, int out_size)
{
    const float* Q = (const float*)d_in[0];
    const float* K = (const float*)d_in[1];
    const float* V = (const float*)d_in[2];
    const int*   M = (const int*)d_in[3];
    float*       O = (float*)d_out;

    cudaFuncSetAttribute(attn_kernel, cudaFuncAttributeMaxDynamicSharedMemorySize, SMEM_BYTES);

    dim3 grid(SDIM / BM, BHDIM);
    attn_kernel<<<grid, THREADS, SMEM_BYTES>>>(Q, K, V, M, O);
}

// round 3
// speedup vs baseline: 1.7699x; 1.7699x over previous
#include <cuda_runtime.h>
#include <cuda_fp16.h>
#include <cstdint>

#define SDIM 2048
#define DDIM 64
#define BHDIM 32         // B*H
#define BM 128           // query rows per CTA
#define BN 64            // keys per iteration
#define NITER (SDIM/BN)  // 32
#define THREADS 256      // 8 warps x 16 q-rows
#define HSTR 72          // halves per smem row (144B: conflict-free ldmatrix, 9*16B)
#define ROWB 144

#define QS_BYTES (BM*ROWB)          // 18432
#define TS_BYTES (BN*ROWB)          // 9216 per K/V stage
#define SMEM_BYTES (QS_BYTES + 4*TS_BYTES)   // Q + K0 K1 V0 V1 = 55296

__device__ __forceinline__ uint32_t packh2(float x, float y) {
    __half2 h = __floats2half2_rn(x, y);
    return *reinterpret_cast<uint32_t*>(&h);
}

__device__ __forceinline__ void ldsm4(uint32_t& r0, uint32_t& r1, uint32_t& r2, uint32_t& r3,
                                      uint32_t addr) {
    asm volatile("ldmatrix.sync.aligned.m8n8.x4.shared.b16 {%0,%1,%2,%3},[%4];\n"
                 : "=r"(r0), "=r"(r1), "=r"(r2), "=r"(r3) : "r"(addr));
}

__device__ __forceinline__ void ldsm4t(uint32_t& r0, uint32_t& r1, uint32_t& r2, uint32_t& r3,
                                       uint32_t addr) {
    asm volatile("ldmatrix.sync.aligned.m8n8.x4.trans.shared.b16 {%0,%1,%2,%3},[%4];\n"
                 : "=r"(r0), "=r"(r1), "=r"(r2), "=r"(r3) : "r"(addr));
}

__device__ __forceinline__ void mma_f16(float d[4],
                                        uint32_t a0, uint32_t a1, uint32_t a2, uint32_t a3,
                                        uint32_t b0, uint32_t b1) {
    asm volatile(
        "mma.sync.aligned.m16n8k16.row.col.f32.f16.f16.f32 "
        "{%0,%1,%2,%3},{%4,%5,%6,%7},{%8,%9},{%0,%1,%2,%3};\n"
        : "+f"(d[0]), "+f"(d[1]), "+f"(d[2]), "+f"(d[3])
        : "r"(a0), "r"(a1), "r"(a2), "r"(a3), "r"(b0), "r"(b1));
}

__global__ void __launch_bounds__(THREADS, 2)
attn_kernel(const float* __restrict__ Q, const float* __restrict__ K,
            const float* __restrict__ V, const int* __restrict__ M,
            float* __restrict__ O)
{
    extern __shared__ char smem[];
    const uint32_t sbase = (uint32_t)__cvta_generic_to_shared(smem);
    const uint32_t qsB = sbase;
    const uint32_t ksB = sbase + QS_BYTES;
    const uint32_t vsB = sbase + QS_BYTES + 2 * TS_BYTES;

    const int tid  = threadIdx.x;
    const int warp = tid >> 5;
    const int lane = tid & 31;
    const int gi   = lane >> 2;
    const int ci   = lane & 3;

    const int q0 = blockIdx.x * BM;
    const int bh = blockIdx.y;

    const size_t baseQ  = ((size_t)bh * SDIM + q0) * DDIM;
    const size_t baseKV = (size_t)bh * SDIM * DDIM;
    const size_t baseM  = (size_t)bh * SDIM * SDIM;

    // ---- load Q tile -> fp16 smem ----
#pragma unroll
    for (int i = 0; i < 8; i++) {
        int idx = i * THREADS + tid;
        int row = idx >> 4;
        int c4  = (idx & 15) << 2;
        float4 v = *reinterpret_cast<const float4*>(Q + baseQ + (size_t)row * DDIM + c4);
        uint2 h = make_uint2(packh2(v.x, v.y), packh2(v.z, v.w));
        *reinterpret_cast<uint2*>(smem + row * ROWB + c4 * 2) = h;
    }

    // ---- prefetch K0/V0 (global fp32 -> fp16 regs) ----
    uint32_t kpre[8], vpre[8];
    {
#pragma unroll
        for (int i = 0; i < 4; i++) {
            int idx = i * THREADS + tid;
            int row = idx >> 4;
            int c4  = (idx & 15) << 2;
            float4 kv = *reinterpret_cast<const float4*>(K + baseKV + (size_t)row * DDIM + c4);
            kpre[2 * i]     = packh2(kv.x, kv.y);
            kpre[2 * i + 1] = packh2(kv.z, kv.w);
            float4 vv = *reinterpret_cast<const float4*>(V + baseKV + (size_t)row * DDIM + c4);
            vpre[2 * i]     = packh2(vv.x, vv.y);
            vpre[2 * i + 1] = packh2(vv.z, vv.w);
        }
    }

    __syncthreads();   // Q visible

    // ---- Q fragments -> registers (held for whole kernel) ----
    // A-frag lane pattern: m0 rows 0-7, m1 rows 8-15, m2 rows 0-7 col+8, m3 rows 8-15 col+8
    const int rlq = (lane & 7) + (lane & 8);
    const int clq = (lane & 16) >> 1;
    uint32_t qf[4][4];
    {
        uint32_t qaddr = qsB + (uint32_t)((warp * 16 + rlq) * ROWB + clq * 2);
#pragma unroll
        for (int t = 0; t < 4; t++)
            ldsm4(qf[t][0], qf[t][1], qf[t][2], qf[t][3], qaddr + t * 32);
    }

    // ---- STS tile 0 into stage 0 ----
#pragma unroll
    for (int i = 0; i < 4; i++) {
        int idx = i * THREADS + tid;
        int row = idx >> 4;
        int c4  = (idx & 15) << 2;
        *reinterpret_cast<uint2*>(smem + QS_BYTES + row * ROWB + c4 * 2) =
            make_uint2(kpre[2 * i], kpre[2 * i + 1]);
        *reinterpret_cast<uint2*>(smem + QS_BYTES + 2 * TS_BYTES + row * ROWB + c4 * 2) =
            make_uint2(vpre[2 * i], vpre[2 * i + 1]);
    }
    __syncthreads();

    const float NEG_INF = __int_as_float(0xff800000);
    float oacc[8][4];
#pragma unroll
    for (int i = 0; i < 8; i++)
#pragma unroll
        for (int j = 0; j < 4; j++) oacc[i][j] = 0.f;
    float m0 = NEG_INF, m1 = NEG_INF, l0 = 0.f, l1 = 0.f;

    const int* mrow0 = M + baseM + (size_t)(q0 + warp * 16 + gi) * SDIM + 2 * ci;
    const int* mrow1 = mrow0 + (size_t)8 * SDIM;

    // K B-frag lane pattern: m0 (r, c), m1 (r, c+8), m2 (r+8, c), m3 (r+8, c+8)
    const int rlk = (lane & 7) + ((lane & 16) >> 1);
    const int clk = (lane & 8);
    // V B-frag (trans) lane pattern: m0 (r, c), m1 (r+8, c), m2 (r, c+8), m3 (r+8, c+8)
    const int rlv = (lane & 7) + (lane & 8);
    const int clv = (lane & 16) >> 1;

    for (int it = 0; it < NITER; ++it) {
        const int st = it & 1;

        // prefetch next K/V tile into registers (covered by compute below)
        if (it + 1 < NITER) {
            const int k0n = (it + 1) * BN;
#pragma unroll
            for (int i = 0; i < 4; i++) {
                int idx = i * THREADS + tid;
                int row = idx >> 4;
                int c4  = (idx & 15) << 2;
                float4 kv = *reinterpret_cast<const float4*>(K + baseKV + (size_t)(k0n + row) * DDIM + c4);
                kpre[2 * i]     = packh2(kv.x, kv.y);
                kpre[2 * i + 1] = packh2(kv.z, kv.w);
                float4 vv = *reinterpret_cast<const float4*>(V + baseKV + (size_t)(k0n + row) * DDIM + c4);
                vpre[2 * i]     = packh2(vv.x, vv.y);
                vpre[2 * i + 1] = packh2(vv.z, vv.w);
            }
        }

        // ---- S = Q K^T  (16 x 64 per warp) ----
        float sacc[8][4];
#pragma unroll
        for (int i = 0; i < 8; i++)
#pragma unroll
            for (int j = 0; j < 4; j++) sacc[i][j] = 0.f;

        {
            uint32_t kaddr = ksB + (uint32_t)(st * TS_BYTES + rlk * ROWB + clk * 2);
#pragma unroll
            for (int t = 0; t < 4; t++) {
#pragma unroll
                for (int j = 0; j < 4; j++) {
                    uint32_t b0, b1, b2, b3;
                    ldsm4(b0, b1, b2, b3, kaddr + (uint32_t)(j * 16 * ROWB + t * 32));
                    mma_f16(sacc[2 * j],     qf[t][0], qf[t][1], qf[t][2], qf[t][3], b0, b1);
                    mma_f16(sacc[2 * j + 1], qf[t][0], qf[t][1], qf[t][2], qf[t][3], b2, b3);
                }
            }
        }

        // ---- mask + scale ----
        const int kbase = it * BN;
#pragma unroll
        for (int nt = 0; nt < 8; nt++) {
            int2 mm0 = *reinterpret_cast<const int2*>(mrow0 + kbase + 8 * nt);
            int2 mm1 = *reinterpret_cast<const int2*>(mrow1 + kbase + 8 * nt);
            sacc[nt][0] = mm0.x ? -1e9f : sacc[nt][0] * 0.125f;
            sacc[nt][1] = mm0.y ? -1e9f : sacc[nt][1] * 0.125f;
            sacc[nt][2] = mm1.x ? -1e9f : sacc[nt][2] * 0.125f;
            sacc[nt][3] = mm1.y ? -1e9f : sacc[nt][3] * 0.125f;
        }

        // ---- online softmax ----
        float rm0 = NEG_INF, rm1 = NEG_INF;
#pragma unroll
        for (int nt = 0; nt < 8; nt++) {
            rm0 = fmaxf(rm0, fmaxf(sacc[nt][0], sacc[nt][1]));
            rm1 = fmaxf(rm1, fmaxf(sacc[nt][2], sacc[nt][3]));
        }
        rm0 = fmaxf(rm0, __shfl_xor_sync(0xffffffffu, rm0, 1));
        rm0 = fmaxf(rm0, __shfl_xor_sync(0xffffffffu, rm0, 2));
        rm1 = fmaxf(rm1, __shfl_xor_sync(0xffffffffu, rm1, 1));
        rm1 = fmaxf(rm1, __shfl_xor_sync(0xffffffffu, rm1, 2));

        float mn0 = fmaxf(m0, rm0), mn1 = fmaxf(m1, rm1);
        float al0 = __expf(m0 - mn0), al1 = __expf(m1 - mn1);

        float rs0 = 0.f, rs1 = 0.f;
#pragma unroll
        for (int nt = 0; nt < 8; nt++) {
            sacc[nt][0] = __expf(sacc[nt][0] - mn0);
            sacc[nt][1] = __expf(sacc[nt][1] - mn0);
            sacc[nt][2] = __expf(sacc[nt][2] - mn1);
            sacc[nt][3] = __expf(sacc[nt][3] - mn1);
            rs0 += sacc[nt][0] + sacc[nt][1];
            rs1 += sacc[nt][2] + sacc[nt][3];
        }
        rs0 += __shfl_xor_sync(0xffffffffu, rs0, 1);
        rs0 += __shfl_xor_sync(0xffffffffu, rs0, 2);
        rs1 += __shfl_xor_sync(0xffffffffu, rs1, 1);
        rs1 += __shfl_xor_sync(0xffffffffu, rs1, 2);

        l0 = l0 * al0 + rs0;
        l1 = l1 * al1 + rs1;
        m0 = mn0; m1 = mn1;

#pragma unroll
        for (int nd = 0; nd < 8; nd++) {
            oacc[nd][0] *= al0; oacc[nd][1] *= al0;
            oacc[nd][2] *= al1; oacc[nd][3] *= al1;
        }

        // ---- O += P V : C-layout of S == A-layout of P in fp16 (no shuffles) ----
        {
            uint32_t vaddr = vsB + (uint32_t)(st * TS_BYTES + rlv * ROWB + clv * 2);
#pragma unroll
            for (int t = 0; t < 4; t++) {
                uint32_t a0 = packh2(sacc[2 * t][0],     sacc[2 * t][1]);
                uint32_t a1 = packh2(sacc[2 * t][2],     sacc[2 * t][3]);
                uint32_t a2 = packh2(sacc[2 * t + 1][0], sacc[2 * t + 1][1]);
                uint32_t a3 = packh2(sacc[2 * t + 1][2], sacc[2 * t + 1][3]);
#pragma unroll
                for (int dj = 0; dj < 4; dj++) {
                    uint32_t b0, b1, b2, b3;
                    ldsm4t(b0, b1, b2, b3, vaddr + (uint32_t)(t * 16 * ROWB + dj * 32));
                    mma_f16(oacc[2 * dj],     a0, a1, a2, a3, b0, b1);
                    mma_f16(oacc[2 * dj + 1], a0, a1, a2, a3, b2, b3);
                }
            }
        }

        // ---- commit prefetched tile to the other stage ----
        if (it + 1 < NITER) {
            __syncthreads();   // all warps done reading stage st^1 (iter it-1)
#pragma unroll
            for (int i = 0; i < 4; i++) {
                int idx = i * THREADS + tid;
                int row = idx >> 4;
                int c4  = (idx & 15) << 2;
                *reinterpret_cast<uint2*>(smem + QS_BYTES + (st ^ 1) * TS_BYTES + row * ROWB + c4 * 2) =
                    make_uint2(kpre[2 * i], kpre[2 * i + 1]);
                *reinterpret_cast<uint2*>(smem + QS_BYTES + 2 * TS_BYTES + (st ^ 1) * TS_BYTES + row * ROWB + c4 * 2) =
                    make_uint2(vpre[2 * i], vpre[2 * i + 1]);
            }
            __syncthreads();   // new tile visible
        }
    }

    // ---- epilogue: O / l ----
    const float il0 = 1.f / l0;
    const float il1 = 1.f / l1;
    float* o0 = O + ((size_t)bh * SDIM + q0 + warp * 16 + gi) * DDIM;
    float* o1 = o0 + 8 * DDIM;
#pragma unroll
    for (int nd = 0; nd < 8; nd++) {
        int col = 8 * nd + 2 * ci;
        float2 r0 = make_float2(oacc[nd][0] * il0, oacc[nd][1] * il0);
        float2 r1 = make_float2(oacc[nd][2] * il1, oacc[nd][3] * il1);
        *reinterpret_cast<float2*>(o0 + col) = r0;
        *reinterpret_cast<float2*>(o1 + col) = r1;
    }
}

extern "C" void kernel_launch(void* const* d_in, const int* in_sizes, int n_in,
                              void* d_out, int out_size)
{
    const float* Q = (const float*)d_in[0];
    const float* K = (const float*)d_in[1];
    const float* V = (const float*)d_in[2];
    const int*   M = (const int*)d_in[3];
    float*       O = (float*)d_out;

    cudaFuncSetAttribute(attn_kernel, cudaFuncAttributeMaxDynamicSharedMemorySize, SMEM_BYTES);

    dim3 grid(SDIM / BM, BHDIM);
    attn_kernel<<<grid, THREADS, SMEM_BYTES>>>(Q, K, V, M, O);
}

// round 4
// speedup vs baseline: 1.9021x; 1.0747x over previous
#include <cuda_runtime.h>
#include <cuda_fp16.h>
#include <cstdint>

#define SDIM 2048
#define DDIM 64
#define BHDIM 32
#define BM 128
#define BN 64
#define NITER (SDIM/BN)      // 32
#define THREADS 128          // 4 warps x 32 q-rows
#define ROWB 144             // bytes per smem row (9 x 16B, conflict-free)
#define NSTAGE 3

#define QS_BYTES (BM*ROWB)               // 18432
#define TS_BYTES (BN*ROWB)               // 9216
#define SMEM_BYTES (QS_BYTES + 2*NSTAGE*TS_BYTES)   // 73728

#define NELEM (BHDIM*SDIM*DDIM)          // 4194304 per tensor

// fp16 copies of Q/K/V (filled by cvt_kernel each launch)
__device__ __half QH[NELEM];
__device__ __half KH[NELEM];
__device__ __half VH[NELEM];

__device__ __forceinline__ uint32_t packh2(float x, float y) {
    __half2 h = __floats2half2_rn(x, y);
    return *reinterpret_cast<uint32_t*>(&h);
}

__device__ __forceinline__ void ldsm4(uint32_t& r0, uint32_t& r1, uint32_t& r2, uint32_t& r3,
                                      uint32_t addr) {
    asm volatile("ldmatrix.sync.aligned.m8n8.x4.shared.b16 {%0,%1,%2,%3},[%4];\n"
                 : "=r"(r0), "=r"(r1), "=r"(r2), "=r"(r3) : "r"(addr));
}
__device__ __forceinline__ void ldsm4t(uint32_t& r0, uint32_t& r1, uint32_t& r2, uint32_t& r3,
                                       uint32_t addr) {
    asm volatile("ldmatrix.sync.aligned.m8n8.x4.trans.shared.b16 {%0,%1,%2,%3},[%4];\n"
                 : "=r"(r0), "=r"(r1), "=r"(r2), "=r"(r3) : "r"(addr));
}
__device__ __forceinline__ void mma_f16(float d[4],
                                        uint32_t a0, uint32_t a1, uint32_t a2, uint32_t a3,
                                        uint32_t b0, uint32_t b1) {
    asm volatile(
        "mma.sync.aligned.m16n8k16.row.col.f32.f16.f16.f32 "
        "{%0,%1,%2,%3},{%4,%5,%6,%7},{%8,%9},{%0,%1,%2,%3};\n"
        : "+f"(d[0]), "+f"(d[1]), "+f"(d[2]), "+f"(d[3])
        : "r"(a0), "r"(a1), "r"(a2), "r"(a3), "r"(b0), "r"(b1));
}
__device__ __forceinline__ void cp16(uint32_t saddr, const void* g) {
    asm volatile("cp.async.cg.shared.global [%0], [%1], 16;\n" :: "r"(saddr), "l"(g));
}

// ---- fp32 -> fp16 pre-pass ----
__global__ void cvt_kernel(const float* __restrict__ Q, const float* __restrict__ K,
                           const float* __restrict__ V)
{
    const float* src = (blockIdx.y == 0) ? Q : (blockIdx.y == 1) ? K : V;
    __half* dst = (blockIdx.y == 0) ? QH : (blockIdx.y == 1) ? KH : VH;
    int i = (blockIdx.x * blockDim.x + threadIdx.x) * 4;
    float4 v = *reinterpret_cast<const float4*>(src + i);
    uint2 h = make_uint2(packh2(v.x, v.y), packh2(v.z, v.w));
    *reinterpret_cast<uint2*>(dst + i) = h;
}

__global__ void __launch_bounds__(THREADS, 2)
attn_kernel(const int* __restrict__ M, float* __restrict__ O)
{
    extern __shared__ char smem[];
    const uint32_t sbase = (uint32_t)__cvta_generic_to_shared(smem);
    const uint32_t qsB = sbase;
    const uint32_t ksB = sbase + QS_BYTES;
    const uint32_t vsB = sbase + QS_BYTES + NSTAGE * TS_BYTES;

    const int tid  = threadIdx.x;
    const int warp = tid >> 5;
    const int lane = tid & 31;
    const int gi   = lane >> 2;
    const int ci   = lane & 3;

    const int q0 = blockIdx.x * BM;
    const int bh = blockIdx.y;

    const size_t baseQ  = ((size_t)bh * SDIM + q0) * DDIM;   // half elems
    const size_t baseKV = (size_t)bh * SDIM * DDIM;
    const size_t baseM  = (size_t)bh * SDIM * SDIM;

    const char* QHb = (const char*)QH + baseQ * 2;
    const char* KHb = (const char*)KH + baseKV * 2;
    const char* VHb = (const char*)VH + baseKV * 2;

    // ---- prologue: Q tile + K/V tiles 0,1 via cp.async ----
    {
#pragma unroll
        for (int i = 0; i < 8; i++) {               // Q: 128 rows x 8 chunks
            int idx = i * THREADS + tid;
            int row = idx >> 3;
            int cb  = (idx & 7) << 4;
            cp16(qsB + (uint32_t)(row * ROWB + cb), QHb + row * DDIM * 2 + cb);
        }
        asm volatile("cp.async.commit_group;\n");
    }
#pragma unroll
    for (int t = 0; t < 2; t++) {
        uint32_t kd = ksB + t * TS_BYTES;
        uint32_t vd = vsB + t * TS_BYTES;
        const char* gk = KHb + (size_t)t * BN * DDIM * 2;
        const char* gv = VHb + (size_t)t * BN * DDIM * 2;
#pragma unroll
        for (int i = 0; i < 4; i++) {               // 64 rows x 8 chunks
            int idx = i * THREADS + tid;
            int row = idx >> 3;
            int cb  = (idx & 7) << 4;
            cp16(kd + (uint32_t)(row * ROWB + cb), gk + row * DDIM * 2 + cb);
            cp16(vd + (uint32_t)(row * ROWB + cb), gv + row * DDIM * 2 + cb);
        }
        asm volatile("cp.async.commit_group;\n");
    }

    asm volatile("cp.async.wait_group 2;\n");       // Q done
    __syncthreads();

    // ---- Q fragments: 2 m-tiles x 4 k-chunks ----
    const int rlq = (lane & 7) + (lane & 8);
    const int clq = (lane & 16) >> 1;
    uint32_t qf[2][4][4];
#pragma unroll
    for (int m = 0; m < 2; m++) {
        uint32_t qaddr = qsB + (uint32_t)((warp * 32 + m * 16 + rlq) * ROWB + clq * 2);
#pragma unroll
        for (int t = 0; t < 4; t++)
            ldsm4(qf[m][t][0], qf[m][t][1], qf[m][t][2], qf[m][t][3], qaddr + t * 32);
    }

    const float NEG_INF = __int_as_float(0xff800000);
    float oacc[2][8][4];
#pragma unroll
    for (int m = 0; m < 2; m++)
#pragma unroll
        for (int i = 0; i < 8; i++)
#pragma unroll
            for (int j = 0; j < 4; j++) oacc[m][i][j] = 0.f;
    float mx[2][2], ls[2][2];
#pragma unroll
    for (int m = 0; m < 2; m++) { mx[m][0] = mx[m][1] = NEG_INF; ls[m][0] = ls[m][1] = 0.f; }

    const int* mbase = M + baseM + (size_t)(q0 + warp * 32 + gi) * SDIM + 2 * ci;

    const int rlk = (lane & 7) + ((lane & 16) >> 1);
    const int clk = (lane & 8);
    const int rlv = (lane & 7) + (lane & 8);
    const int clv = (lane & 16) >> 1;

    for (int it = 0; it < NITER; ++it) {
        const int st = it % NSTAGE;

        __syncthreads();   // everyone done reading the stage we are about to overwrite
        if (it + 2 < NITER) {
            const int tn = it + 2;
            const int sn = tn % NSTAGE;
            uint32_t kd = ksB + sn * TS_BYTES;
            uint32_t vd = vsB + sn * TS_BYTES;
            const char* gk = KHb + (size_t)tn * BN * DDIM * 2;
            const char* gv = VHb + (size_t)tn * BN * DDIM * 2;
#pragma unroll
            for (int i = 0; i < 4; i++) {
                int idx = i * THREADS + tid;
                int row = idx >> 3;
                int cb  = (idx & 7) << 4;
                cp16(kd + (uint32_t)(row * ROWB + cb), gk + row * DDIM * 2 + cb);
                cp16(vd + (uint32_t)(row * ROWB + cb), gv + row * DDIM * 2 + cb);
            }
            asm volatile("cp.async.commit_group;\n");
            asm volatile("cp.async.wait_group 2;\n");
        } else if (it + 1 < NITER) {
            asm volatile("cp.async.wait_group 1;\n");
        } else {
            asm volatile("cp.async.wait_group 0;\n");
        }
        __syncthreads();   // tile it visible to all warps

        // ---- S = Q K^T : 32 x 64 per warp ----
        float sacc[2][8][4];
#pragma unroll
        for (int m = 0; m < 2; m++)
#pragma unroll
            for (int i = 0; i < 8; i++)
#pragma unroll
                for (int j = 0; j < 4; j++) sacc[m][i][j] = 0.f;
        {
            uint32_t kaddr = ksB + (uint32_t)(st * TS_BYTES + rlk * ROWB + clk * 2);
#pragma unroll
            for (int t = 0; t < 4; t++) {
#pragma unroll
                for (int j = 0; j < 4; j++) {
                    uint32_t b0, b1, b2, b3;
                    ldsm4(b0, b1, b2, b3, kaddr + (uint32_t)(j * 16 * ROWB + t * 32));
#pragma unroll
                    for (int m = 0; m < 2; m++) {
                        mma_f16(sacc[m][2 * j],     qf[m][t][0], qf[m][t][1], qf[m][t][2], qf[m][t][3], b0, b1);
                        mma_f16(sacc[m][2 * j + 1], qf[m][t][0], qf[m][t][1], qf[m][t][2], qf[m][t][3], b2, b3);
                    }
                }
            }
        }

        // ---- mask + scale + online softmax (per m-tile) ----
        const int kbase = it * BN;
#pragma unroll
        for (int m = 0; m < 2; m++) {
            const int* mr0 = mbase + (size_t)(m * 16) * SDIM + kbase;
            const int* mr1 = mr0 + (size_t)8 * SDIM;
#pragma unroll
            for (int nt = 0; nt < 8; nt++) {
                int2 mm0 = __ldcs(reinterpret_cast<const int2*>(mr0 + 8 * nt));
                int2 mm1 = __ldcs(reinterpret_cast<const int2*>(mr1 + 8 * nt));
                sacc[m][nt][0] = mm0.x ? -1e9f : sacc[m][nt][0] * 0.125f;
                sacc[m][nt][1] = mm0.y ? -1e9f : sacc[m][nt][1] * 0.125f;
                sacc[m][nt][2] = mm1.x ? -1e9f : sacc[m][nt][2] * 0.125f;
                sacc[m][nt][3] = mm1.y ? -1e9f : sacc[m][nt][3] * 0.125f;
            }

            float rm0 = NEG_INF, rm1 = NEG_INF;
#pragma unroll
            for (int nt = 0; nt < 8; nt++) {
                rm0 = fmaxf(rm0, fmaxf(sacc[m][nt][0], sacc[m][nt][1]));
                rm1 = fmaxf(rm1, fmaxf(sacc[m][nt][2], sacc[m][nt][3]));
            }
            rm0 = fmaxf(rm0, __shfl_xor_sync(0xffffffffu, rm0, 1));
            rm0 = fmaxf(rm0, __shfl_xor_sync(0xffffffffu, rm0, 2));
            rm1 = fmaxf(rm1, __shfl_xor_sync(0xffffffffu, rm1, 1));
            rm1 = fmaxf(rm1, __shfl_xor_sync(0xffffffffu, rm1, 2));

            float mn0 = fmaxf(mx[m][0], rm0), mn1 = fmaxf(mx[m][1], rm1);
            float al0 = __expf(mx[m][0] - mn0), al1 = __expf(mx[m][1] - mn1);

            float rs0 = 0.f, rs1 = 0.f;
#pragma unroll
            for (int nt = 0; nt < 8; nt++) {
                sacc[m][nt][0] = __expf(sacc[m][nt][0] - mn0);
                sacc[m][nt][1] = __expf(sacc[m][nt][1] - mn0);
                sacc[m][nt][2] = __expf(sacc[m][nt][2] - mn1);
                sacc[m][nt][3] = __expf(sacc[m][nt][3] - mn1);
                rs0 += sacc[m][nt][0] + sacc[m][nt][1];
                rs1 += sacc[m][nt][2] + sacc[m][nt][3];
            }
            rs0 += __shfl_xor_sync(0xffffffffu, rs0, 1);
            rs0 += __shfl_xor_sync(0xffffffffu, rs0, 2);
            rs1 += __shfl_xor_sync(0xffffffffu, rs1, 1);
            rs1 += __shfl_xor_sync(0xffffffffu, rs1, 2);

            ls[m][0] = ls[m][0] * al0 + rs0;
            ls[m][1] = ls[m][1] * al1 + rs1;
            mx[m][0] = mn0; mx[m][1] = mn1;

#pragma unroll
            for (int nd = 0; nd < 8; nd++) {
                oacc[m][nd][0] *= al0; oacc[m][nd][1] *= al0;
                oacc[m][nd][2] *= al1; oacc[m][nd][3] *= al1;
            }
        }

        // ---- O += P V (fp16 C-layout == A-layout, no shuffles) ----
        {
            uint32_t vaddr = vsB + (uint32_t)(st * TS_BYTES + rlv * ROWB + clv * 2);
#pragma unroll
            for (int t = 0; t < 4; t++) {
                uint32_t a[2][4];
#pragma unroll
                for (int m = 0; m < 2; m++) {
                    a[m][0] = packh2(sacc[m][2 * t][0],     sacc[m][2 * t][1]);
                    a[m][1] = packh2(sacc[m][2 * t][2],     sacc[m][2 * t][3]);
                    a[m][2] = packh2(sacc[m][2 * t + 1][0], sacc[m][2 * t + 1][1]);
                    a[m][3] = packh2(sacc[m][2 * t + 1][2], sacc[m][2 * t + 1][3]);
                }
#pragma unroll
                for (int dj = 0; dj < 4; dj++) {
                    uint32_t b0, b1, b2, b3;
                    ldsm4t(b0, b1, b2, b3, vaddr + (uint32_t)(t * 16 * ROWB + dj * 32));
#pragma unroll
                    for (int m = 0; m < 2; m++) {
                        mma_f16(oacc[m][2 * dj],     a[m][0], a[m][1], a[m][2], a[m][3], b0, b1);
                        mma_f16(oacc[m][2 * dj + 1], a[m][0], a[m][1], a[m][2], a[m][3], b2, b3);
                    }
                }
            }
        }
    }

    // ---- epilogue ----
#pragma unroll
    for (int m = 0; m < 2; m++) {
        const float il0 = 1.f / ls[m][0];
        const float il1 = 1.f / ls[m][1];
        float* o0 = O + ((size_t)bh * SDIM + q0 + warp * 32 + m * 16 + gi) * DDIM;
        float* o1 = o0 + 8 * DDIM;
#pragma unroll
        for (int nd = 0; nd < 8; nd++) {
            int col = 8 * nd + 2 * ci;
            *reinterpret_cast<float2*>(o0 + col) =
                make_float2(oacc[m][nd][0] * il0, oacc[m][nd][1] * il0);
            *reinterpret_cast<float2*>(o1 + col) =
                make_float2(oacc[m][nd][2] * il1, oacc[m][nd][3] * il1);
        }
    }
}

extern "C" void kernel_launch(void* const* d_in, const int* in_sizes, int n_in,
                              void* d_out, int out_size)
{
    const float* Q = (const float*)d_in[0];
    const float* K = (const float*)d_in[1];
    const float* V = (const float*)d_in[2];
    const int*   M = (const int*)d_in[3];
    float*       O = (float*)d_out;

    dim3 cgrid(NELEM / (256 * 4), 3);
    cvt_kernel<<<cgrid, 256>>>(Q, K, V);

    cudaFuncSetAttribute(attn_kernel, cudaFuncAttributeMaxDynamicSharedMemorySize, SMEM_BYTES);
    dim3 grid(SDIM / BM, BHDIM);
    attn_kernel<<<grid, THREADS, SMEM_BYTES>>>(M, O);
}

// round 5
// speedup vs baseline: 2.0665x; 1.0864x over previous
#include <cuda_runtime.h>
#include <cuda_fp16.h>
#include <cstdint>

#define SDIM 2048
#define DDIM 64
#define BHDIM 32
#define BM 128
#define BN 32
#define NITER (SDIM/BN)      // 64
#define THREADS 128          // 4 warps x 32 q-rows
#define ROWB 144             // bytes per smem row (conflict-free ldsm + 2-way mask)
#define NSTAGE 3

#define QS_BYTES (BM*ROWB)               // 18432
#define KS_BYTES (BN*ROWB)               // 4608 (K or V stage)
#define MS_BYTES (BM*ROWB)               // 18432 (mask stage: 128 rows x 32 ints, 144B stride)
#define SMEM_BYTES (QS_BYTES + NSTAGE*(2*KS_BYTES + MS_BYTES))   // 101376

#define NELEM (BHDIM*SDIM*DDIM)

__device__ __half QH[NELEM];
__device__ __half KH[NELEM];
__device__ __half VH[NELEM];

__device__ __forceinline__ uint32_t packh2(float x, float y) {
    __half2 h = __floats2half2_rn(x, y);
    return *reinterpret_cast<uint32_t*>(&h);
}
__device__ __forceinline__ void ldsm4(uint32_t& r0, uint32_t& r1, uint32_t& r2, uint32_t& r3,
                                      uint32_t addr) {
    asm volatile("ldmatrix.sync.aligned.m8n8.x4.shared.b16 {%0,%1,%2,%3},[%4];\n"
                 : "=r"(r0), "=r"(r1), "=r"(r2), "=r"(r3) : "r"(addr));
}
__device__ __forceinline__ void ldsm4t(uint32_t& r0, uint32_t& r1, uint32_t& r2, uint32_t& r3,
                                       uint32_t addr) {
    asm volatile("ldmatrix.sync.aligned.m8n8.x4.trans.shared.b16 {%0,%1,%2,%3},[%4];\n"
                 : "=r"(r0), "=r"(r1), "=r"(r2), "=r"(r3) : "r"(addr));
}
__device__ __forceinline__ void mma_f16(float d[4],
                                        uint32_t a0, uint32_t a1, uint32_t a2, uint32_t a3,
                                        uint32_t b0, uint32_t b1) {
    asm volatile(
        "mma.sync.aligned.m16n8k16.row.col.f32.f16.f16.f32 "
        "{%0,%1,%2,%3},{%4,%5,%6,%7},{%8,%9},{%0,%1,%2,%3};\n"
        : "+f"(d[0]), "+f"(d[1]), "+f"(d[2]), "+f"(d[3])
        : "r"(a0), "r"(a1), "r"(a2), "r"(a3), "r"(b0), "r"(b1));
}
__device__ __forceinline__ void cp16(uint32_t saddr, const void* g) {
    asm volatile("cp.async.cg.shared.global [%0], [%1], 16;\n" :: "r"(saddr), "l"(g));
}
__device__ __forceinline__ int2 lds64(uint32_t addr) {
    int2 v;
    asm volatile("ld.shared.v2.u32 {%0,%1},[%2];\n" : "=r"(v.x), "=r"(v.y) : "r"(addr));
    return v;
}

// ---- fp32 -> fp16 pre-pass ----
__global__ void cvt_kernel(const float* __restrict__ Q, const float* __restrict__ K,
                           const float* __restrict__ V)
{
    const float* src = (blockIdx.y == 0) ? Q : (blockIdx.y == 1) ? K : V;
    __half* dst = (blockIdx.y == 0) ? QH : (blockIdx.y == 1) ? KH : VH;
    int i = (blockIdx.x * blockDim.x + threadIdx.x) * 4;
    float4 v = *reinterpret_cast<const float4*>(src + i);
    *reinterpret_cast<uint2*>(dst + i) = make_uint2(packh2(v.x, v.y), packh2(v.z, v.w));
}

__global__ void __launch_bounds__(THREADS, 2)
attn_kernel(const int* __restrict__ M, float* __restrict__ O)
{
    extern __shared__ char smem[];
    const uint32_t sbase = (uint32_t)__cvta_generic_to_shared(smem);
    const uint32_t qsB = sbase;
    const uint32_t ksB = sbase + QS_BYTES;
    const uint32_t vsB = ksB + NSTAGE * KS_BYTES;
    const uint32_t msB = vsB + NSTAGE * KS_BYTES;

    const int tid  = threadIdx.x;
    const int warp = tid >> 5;
    const int lane = tid & 31;
    const int gi   = lane >> 2;
    const int ci   = lane & 3;

    const int q0 = blockIdx.x * BM;
    const int bh = blockIdx.y;

    const size_t baseQ  = ((size_t)bh * SDIM + q0) * DDIM;
    const size_t baseKV = (size_t)bh * SDIM * DDIM;

    const char* QHb = (const char*)QH + baseQ * 2;
    const char* KHb = (const char*)KH + baseKV * 2;
    const char* VHb = (const char*)VH + baseKV * 2;
    const char* Mb  = (const char*)(M + (size_t)bh * SDIM * SDIM + (size_t)q0 * SDIM);

    // ---- prologue: Q (group 0), then tiles 0,1 of K/V/mask (groups 1,2) ----
#pragma unroll
    for (int i = 0; i < 8; i++) {                  // Q: 128 rows x 8 chunks
        int idx = i * THREADS + tid;
        int row = idx >> 3;
        int cb  = (idx & 7) << 4;
        cp16(qsB + (uint32_t)(row * ROWB + cb), QHb + row * DDIM * 2 + cb);
    }
    asm volatile("cp.async.commit_group;\n");

#pragma unroll
    for (int t = 0; t < 2; t++) {
        const char* gk = KHb + (size_t)t * BN * DDIM * 2;
        const char* gv = VHb + (size_t)t * BN * DDIM * 2;
#pragma unroll
        for (int i = 0; i < 2; i++) {              // K/V: 32 rows x 8 chunks
            int idx = i * THREADS + tid;
            int row = idx >> 3;
            int cb  = (idx & 7) << 4;
            cp16(ksB + (uint32_t)(t * KS_BYTES + row * ROWB + cb), gk + row * DDIM * 2 + cb);
            cp16(vsB + (uint32_t)(t * KS_BYTES + row * ROWB + cb), gv + row * DDIM * 2 + cb);
        }
#pragma unroll
        for (int i = 0; i < 8; i++) {              // mask: 128 rows x 8 chunks (128B/row)
            int idx = i * THREADS + tid;
            int row = idx >> 3;
            int cb  = (idx & 7) << 4;
            cp16(msB + (uint32_t)(t * MS_BYTES + row * ROWB + cb),
                 Mb + (size_t)row * SDIM * 4 + t * BN * 4 + cb);
        }
        asm volatile("cp.async.commit_group;\n");
    }

    asm volatile("cp.async.wait_group 2;\n");      // Q done
    __syncthreads();

    // ---- Q fragments: 2 m-tiles x 4 k-chunks ----
    const int rlq = (lane & 7) + (lane & 8);
    const int clq = (lane & 16) >> 1;
    uint32_t qf[2][4][4];
#pragma unroll
    for (int m = 0; m < 2; m++) {
        uint32_t qaddr = qsB + (uint32_t)((warp * 32 + m * 16 + rlq) * ROWB + clq * 2);
#pragma unroll
        for (int t = 0; t < 4; t++)
            ldsm4(qf[m][t][0], qf[m][t][1], qf[m][t][2], qf[m][t][3], qaddr + t * 32);
    }

    const float NEG_INF = __int_as_float(0xff800000);
    float oacc[2][8][4];
#pragma unroll
    for (int m = 0; m < 2; m++)
#pragma unroll
        for (int i = 0; i < 8; i++)
#pragma unroll
            for (int j = 0; j < 4; j++) oacc[m][i][j] = 0.f;
    float mx[2][2], ls[2][2];
#pragma unroll
    for (int m = 0; m < 2; m++) { mx[m][0] = mx[m][1] = NEG_INF; ls[m][0] = ls[m][1] = 0.f; }

    const int rlk = (lane & 7) + ((lane & 16) >> 1);
    const int clk = (lane & 8);
    const int rlv = (lane & 7) + (lane & 8);
    const int clv = (lane & 16) >> 1;

    for (int it = 0; it < NITER; ++it) {
        const int st = it % NSTAGE;

        __syncthreads();   // all warps done reading the stage we are about to overwrite
        if (it + 2 < NITER) {
            const int tn = it + 2;
            const int sn = tn % NSTAGE;
            const char* gk = KHb + (size_t)tn * BN * DDIM * 2;
            const char* gv = VHb + (size_t)tn * BN * DDIM * 2;
#pragma unroll
            for (int i = 0; i < 2; i++) {
                int idx = i * THREADS + tid;
                int row = idx >> 3;
                int cb  = (idx & 7) << 4;
                cp16(ksB + (uint32_t)(sn * KS_BYTES + row * ROWB + cb), gk + row * DDIM * 2 + cb);
                cp16(vsB + (uint32_t)(sn * KS_BYTES + row * ROWB + cb), gv + row * DDIM * 2 + cb);
            }
#pragma unroll
            for (int i = 0; i < 8; i++) {
                int idx = i * THREADS + tid;
                int row = idx >> 3;
                int cb  = (idx & 7) << 4;
                cp16(msB + (uint32_t)(sn * MS_BYTES + row * ROWB + cb),
                     Mb + (size_t)row * SDIM * 4 + (size_t)tn * BN * 4 + cb);
            }
            asm volatile("cp.async.commit_group;\n");
            asm volatile("cp.async.wait_group 2;\n");
        } else if (it + 1 < NITER) {
            asm volatile("cp.async.wait_group 1;\n");
        } else {
            asm volatile("cp.async.wait_group 0;\n");
        }
        __syncthreads();   // stage st visible to all warps

        // ---- S = Q K^T : 32 x 32 per warp ----
        float sacc[2][4][4];
#pragma unroll
        for (int m = 0; m < 2; m++)
#pragma unroll
            for (int i = 0; i < 4; i++)
#pragma unroll
                for (int j = 0; j < 4; j++) sacc[m][i][j] = 0.f;
        {
            uint32_t kaddr = ksB + (uint32_t)(st * KS_BYTES + rlk * ROWB + clk * 2);
#pragma unroll
            for (int t = 0; t < 4; t++) {
#pragma unroll
                for (int j = 0; j < 2; j++) {
                    uint32_t b0, b1, b2, b3;
                    ldsm4(b0, b1, b2, b3, kaddr + (uint32_t)(j * 16 * ROWB + t * 32));
#pragma unroll
                    for (int m = 0; m < 2; m++) {
                        mma_f16(sacc[m][2 * j],     qf[m][t][0], qf[m][t][1], qf[m][t][2], qf[m][t][3], b0, b1);
                        mma_f16(sacc[m][2 * j + 1], qf[m][t][0], qf[m][t][1], qf[m][t][2], qf[m][t][3], b2, b3);
                    }
                }
            }
        }

        // ---- mask (from smem ring) + scale + online softmax ----
#pragma unroll
        for (int m = 0; m < 2; m++) {
            uint32_t maddr0 = msB + (uint32_t)(st * MS_BYTES + (warp * 32 + m * 16 + gi) * ROWB + 8 * ci);
            uint32_t maddr1 = maddr0 + 8 * ROWB;
#pragma unroll
            for (int nt = 0; nt < 4; nt++) {
                int2 mm0 = lds64(maddr0 + nt * 32);
                int2 mm1 = lds64(maddr1 + nt * 32);
                sacc[m][nt][0] = mm0.x ? -1e9f : sacc[m][nt][0] * 0.125f;
                sacc[m][nt][1] = mm0.y ? -1e9f : sacc[m][nt][1] * 0.125f;
                sacc[m][nt][2] = mm1.x ? -1e9f : sacc[m][nt][2] * 0.125f;
                sacc[m][nt][3] = mm1.y ? -1e9f : sacc[m][nt][3] * 0.125f;
            }

            float rm0 = NEG_INF, rm1 = NEG_INF;
#pragma unroll
            for (int nt = 0; nt < 4; nt++) {
                rm0 = fmaxf(rm0, fmaxf(sacc[m][nt][0], sacc[m][nt][1]));
                rm1 = fmaxf(rm1, fmaxf(sacc[m][nt][2], sacc[m][nt][3]));
            }
            rm0 = fmaxf(rm0, __shfl_xor_sync(0xffffffffu, rm0, 1));
            rm0 = fmaxf(rm0, __shfl_xor_sync(0xffffffffu, rm0, 2));
            rm1 = fmaxf(rm1, __shfl_xor_sync(0xffffffffu, rm1, 1));
            rm1 = fmaxf(rm1, __shfl_xor_sync(0xffffffffu, rm1, 2));

            float mn0 = fmaxf(mx[m][0], rm0), mn1 = fmaxf(mx[m][1], rm1);
            float al0 = __expf(mx[m][0] - mn0), al1 = __expf(mx[m][1] - mn1);

            float rs0 = 0.f, rs1 = 0.f;
#pragma unroll
            for (int nt = 0; nt < 4; nt++) {
                sacc[m][nt][0] = __expf(sacc[m][nt][0] - mn0);
                sacc[m][nt][1] = __expf(sacc[m][nt][1] - mn0);
                sacc[m][nt][2] = __expf(sacc[m][nt][2] - mn1);
                sacc[m][nt][3] = __expf(sacc[m][nt][3] - mn1);
                rs0 += sacc[m][nt][0] + sacc[m][nt][1];
                rs1 += sacc[m][nt][2] + sacc[m][nt][3];
            }
            rs0 += __shfl_xor_sync(0xffffffffu, rs0, 1);
            rs0 += __shfl_xor_sync(0xffffffffu, rs0, 2);
            rs1 += __shfl_xor_sync(0xffffffffu, rs1, 1);
            rs1 += __shfl_xor_sync(0xffffffffu, rs1, 2);

            ls[m][0] = ls[m][0] * al0 + rs0;
            ls[m][1] = ls[m][1] * al1 + rs1;
            mx[m][0] = mn0; mx[m][1] = mn1;

#pragma unroll
            for (int nd = 0; nd < 8; nd++) {
                oacc[m][nd][0] *= al0; oacc[m][nd][1] *= al0;
                oacc[m][nd][2] *= al1; oacc[m][nd][3] *= al1;
            }
        }

        // ---- O += P V ----
        {
            uint32_t vaddr = vsB + (uint32_t)(st * KS_BYTES + rlv * ROWB + clv * 2);
#pragma unroll
            for (int t = 0; t < 2; t++) {
                uint32_t a[2][4];
#pragma unroll
                for (int m = 0; m < 2; m++) {
                    a[m][0] = packh2(sacc[m][2 * t][0],     sacc[m][2 * t][1]);
                    a[m][1] = packh2(sacc[m][2 * t][2],     sacc[m][2 * t][3]);
                    a[m][2] = packh2(sacc[m][2 * t + 1][0], sacc[m][2 * t + 1][1]);
                    a[m][3] = packh2(sacc[m][2 * t + 1][2], sacc[m][2 * t + 1][3]);
                }
#pragma unroll
                for (int dj = 0; dj < 4; dj++) {
                    uint32_t b0, b1, b2, b3;
                    ldsm4t(b0, b1, b2, b3, vaddr + (uint32_t)(t * 16 * ROWB + dj * 32));
#pragma unroll
                    for (int m = 0; m < 2; m++) {
                        mma_f16(oacc[m][2 * dj],     a[m][0], a[m][1], a[m][2], a[m][3], b0, b1);
                        mma_f16(oacc[m][2 * dj + 1], a[m][0], a[m][1], a[m][2], a[m][3], b2, b3);
                    }
                }
            }
        }
    }

    // ---- epilogue ----
#pragma unroll
    for (int m = 0; m < 2; m++) {
        const float il0 = 1.f / ls[m][0];
        const float il1 = 1.f / ls[m][1];
        float* o0 = O + ((size_t)bh * SDIM + q0 + warp * 32 + m * 16 + gi) * DDIM;
        float* o1 = o0 + 8 * DDIM;
#pragma unroll
        for (int nd = 0; nd < 8; nd++) {
            int col = 8 * nd + 2 * ci;
            *reinterpret_cast<float2*>(o0 + col) =
                make_float2(oacc[m][nd][0] * il0, oacc[m][nd][1] * il0);
            *reinterpret_cast<float2*>(o1 + col) =
                make_float2(oacc[m][nd][2] * il1, oacc[m][nd][3] * il1);
        }
    }
}

extern "C" void kernel_launch(void* const* d_in, const int* in_sizes, int n_in,
                              void* d_out, int out_size)
{
    const float* Q = (const float*)d_in[0];
    const float* K = (const float*)d_in[1];
    const float* V = (const float*)d_in[2];
    const int*   M = (const int*)d_in[3];
    float*       O = (float*)d_out;

    dim3 cgrid(NELEM / (256 * 4), 3);
    cvt_kernel<<<cgrid, 256>>>(Q, K, V);

    cudaFuncSetAttribute(attn_kernel, cudaFuncAttributeMaxDynamicSharedMemorySize, SMEM_BYTES);
    dim3 grid(SDIM / BM, BHDIM);
    attn_kernel<<<grid, THREADS, SMEM_BYTES>>>(M, O);
}